// round 9
// baseline (speedup 1.0000x reference)
#include <cuda_runtime.h>
#include <cuda_bf16.h>
#include <math.h>
#include <stdint.h>

// ---------------------------------------------------------------------------
// Output = real part of V: 8192 x 8192 float32 (256 MiB). V = eye with
// closed-form 2x2 Hermitian block exp at (123, 4567).
//
// R8 conclusion: period is pinned by steady-state DRAM write drain
// (268 MB / ~6.5 TB/s ~= 41 us). L2-retention tricks are a no-op on this
// harness. This round: unroll x2 (pair of float4 per thread), persistent
// single-wave grid (148*8 blocks @ 256 thr = 8 CTA/SM, one wave), all
// evict-first stores.
// ---------------------------------------------------------------------------

static constexpr long long N_CONST = 8192;
static constexpr long long NN      = N_CONST * N_CONST;   // 67,108,864
static constexpr long long NPAIR   = NN >> 3;             // 8,388,608 float4-pairs
static constexpr int       CONN_I  = 123;
static constexpr int       CONN_J  = 4567;
// Pair granularity: 8 columns per pair; 1024 pairs per row.
// col 123  -> pairbase 120,  first  float4, component .w
// col 4567 -> pairbase 4560, second float4, component .w
static constexpr int PB_I = (CONN_I / 8) * 8;   // 120
static constexpr int PB_J = (CONN_J / 8) * 8;   // 4560

// Closed-form real parts of exp(1j*H) for the 2x2 Hermitian block.
__device__ __forceinline__ void block_exp_real(
    float a, float b, float cr, float ci,
    float& eii_re, float& ejj_re, float& eij_re, float& eji_re) {
    const float t = 0.5f * (a + b);
    const float d = 0.5f * (a - b);
    const float r = sqrtf(d * d + cr * cr + ci * ci);
    const float sinc = (r > 0.f) ? (sinf(r) / r) : 1.f;
    const float cosr = cosf(r);
    float st, ct;
    sincosf(t, &st, &ct);
    eii_re = ct * cosr - st * (sinc * d);
    ejj_re = ct * cosr + st * (sinc * d);
    eij_re = ct * (-sinc * ci) - st * (sinc * cr);
    eji_re = ct * (sinc * ci) - st * (sinc * cr);
}

// ---------------------------------------------------------------------------
// Fused kernel, unroll x2: zero + diagonal + block patch.
// ---------------------------------------------------------------------------
__global__ void fused_fill_kernel(const float* __restrict__ bii,
                                  const float* __restrict__ bjj,
                                  const float* __restrict__ bij_real,
                                  const float* __restrict__ bij_img,
                                  float4* __restrict__ out4) {
    long long p = (long long)blockIdx.x * blockDim.x + threadIdx.x;
    const long long stride = (long long)gridDim.x * blockDim.x;

    for (; p < NPAIR; p += stride) {
        const int row      = (int)(p >> 10);          // 1024 pairs per row
        const int pairbase = ((int)p & 1023) << 3;    // first of 8 columns

        float4 v0 = make_float4(0.f, 0.f, 0.f, 0.f);
        float4 v1 = make_float4(0.f, 0.f, 0.f, 0.f);

        // Diagonal element among these 8 columns?
        const unsigned d = (unsigned)(row - pairbase);
        if (d < 8u) {
            float* vv = (d < 4u) ? &v0.x : &v1.x;
            vv[d & 3u] = 1.f;
        }

        // 2x2 block entries (taken by <=2 threads):
        //   (123,123)=eii @ row 123, pb 120 (v0.w)
        //   (123,4567)=eij @ row 123, pb 4560 (v1.w)
        //   (4567,123)=eji @ row 4567, pb 120 (v0.w)
        //   (4567,4567)=ejj @ row 4567, pb 4560 (v1.w)
        if ((row == CONN_I || row == CONN_J) &&
            (pairbase == PB_I || pairbase == PB_J)) {
            float eii, ejj, eij, eji;
            block_exp_real(bii[0], bjj[0], bij_real[0], bij_img[0],
                           eii, ejj, eij, eji);
            if (row == CONN_I) {
                if (pairbase == PB_I) v0.w = eii; else v1.w = eij;
            } else {
                if (pairbase == PB_I) v0.w = eji; else v1.w = ejj;
            }
        }

        const long long k = p << 1;
        __stcs(&out4[k],     v0);
        __stcs(&out4[k + 1], v1);
    }
}

// ---------------------------------------------------------------------------
// Fallback path (layout surprise): scalar-safe fill + patches.
// ---------------------------------------------------------------------------
__global__ void fill_zero_scalar(float* __restrict__ out, long long nfloats) {
    long long i = (long long)blockIdx.x * blockDim.x + threadIdx.x;
    const long long stride = (long long)gridDim.x * blockDim.x;
    for (; i < nfloats; i += stride) out[i] = 0.f;
}

__global__ void diag_kernel(float* __restrict__ out) {
    long long i = (long long)blockIdx.x * blockDim.x + threadIdx.x;
    if (i < N_CONST) out[i * (N_CONST + 1)] = 1.f;
}

__global__ void block_kernel(const float* __restrict__ bii,
                             const float* __restrict__ bjj,
                             const float* __restrict__ bij_real,
                             const float* __restrict__ bij_img,
                             float* __restrict__ out) {
    if (threadIdx.x != 0 || blockIdx.x != 0) return;
    float eii, ejj, eij, eji;
    block_exp_real(bii[0], bjj[0], bij_real[0], bij_img[0],
                   eii, ejj, eij, eji);
    out[(long long)CONN_I * N_CONST + CONN_I] = eii;
    out[(long long)CONN_J * N_CONST + CONN_J] = ejj;
    out[(long long)CONN_I * N_CONST + CONN_J] = eij;
    out[(long long)CONN_J * N_CONST + CONN_I] = eji;
}

extern "C" void kernel_launch(void* const* d_in, const int* in_sizes, int n_in,
                              void* d_out, int out_size) {
    if (n_in < 4) return;

    const float* bii      = (const float*)d_in[0];
    const float* bjj      = (const float*)d_in[1];
    const float* bij_real = (const float*)d_in[2];
    const float* bij_img  = (const float*)d_in[3];

    const bool aligned16 = (((uintptr_t)d_out) & 15u) == 0;
    const bool full      = ((long long)out_size == NN);

    if (aligned16 && full) {
        // Persistent single wave: 8 CTAs/SM * 148 SMs, 256 threads each.
        fused_fill_kernel<<<148 * 8, 256>>>(bii, bjj, bij_real, bij_img,
                                            (float4*)d_out);
    } else {
        float* outf = (float*)d_out;
        const long long nfloats = (long long)out_size;
        fill_zero_scalar<<<148 * 32, 256>>>(outf, nfloats);
        if (nfloats >= NN) {
            diag_kernel<<<(int)((N_CONST + 255) / 256), 256>>>(outf);
            block_kernel<<<1, 32>>>(bii, bjj, bij_real, bij_img, outf);
        }
    }
}

// round 10
// speedup vs baseline: 1.8323x; 1.8323x over previous
#include <cuda_runtime.h>
#include <cuda_bf16.h>
#include <math.h>
#include <stdint.h>

// ---------------------------------------------------------------------------
// Output = real part of V: 8192 x 8192 float32 (256 MiB). V = eye with
// closed-form 2x2 Hermitian block exp at (123, 4567).
//
// Final configuration = R7 winner (41.1 us, DRAM-write drain floor):
//  * ONE fused kernel: zero-fill + diagonal + block patch in a single
//    STG.128 pass (saves ~6 us of extra-launch overhead vs 3 kernels).
//  * grid 148*32 = 4736 blocks x 256 threads, grid-stride, one float4 per
//    thread per iteration -> perfectly coalesced 4KB per warp-iteration.
//    (R9 showed per-thread float4 PAIRS de-coalesce STG.128 wavefronts and
//    a 1184-block grid starves the store pipeline: 104 us. Do not repeat.)
//  * __stcs evict-first stores (best measured; L2-retention splits are a
//    no-op on this harness, R8).
// Period is pinned by steady-state DRAM drain: 268 MB / ~6.5 TB/s ~= 41 us.
// ---------------------------------------------------------------------------

static constexpr long long N_CONST = 8192;
static constexpr long long NN      = N_CONST * N_CONST;   // 67,108,864
static constexpr long long N4      = NN >> 2;             // 16,777,216 float4
static constexpr int       CONN_I  = 123;
static constexpr int       CONN_J  = 4567;
static constexpr int CB_I = (CONN_I / 4) * 4;   // 120
static constexpr int CB_J = (CONN_J / 4) * 4;   // 4564

// Closed-form real parts of exp(1j*H) for the 2x2 Hermitian block.
__device__ __forceinline__ void block_exp_real(
    float a, float b, float cr, float ci,
    float& eii_re, float& ejj_re, float& eij_re, float& eji_re) {
    const float t = 0.5f * (a + b);
    const float d = 0.5f * (a - b);
    const float r = sqrtf(d * d + cr * cr + ci * ci);
    const float sinc = (r > 0.f) ? (sinf(r) / r) : 1.f;
    const float cosr = cosf(r);
    float st, ct;
    sincosf(t, &st, &ct);
    eii_re = ct * cosr - st * (sinc * d);
    ejj_re = ct * cosr + st * (sinc * d);
    eij_re = ct * (-sinc * ci) - st * (sinc * cr);
    eji_re = ct * (sinc * ci) - st * (sinc * cr);
}

// ---------------------------------------------------------------------------
// Fused kernel: zero + diagonal + block patch, one pass of STG.128.
// ---------------------------------------------------------------------------
__global__ void fused_fill_kernel(const float* __restrict__ bii,
                                  const float* __restrict__ bjj,
                                  const float* __restrict__ bij_real,
                                  const float* __restrict__ bij_img,
                                  float4* __restrict__ out4) {
    long long k = (long long)blockIdx.x * blockDim.x + threadIdx.x;
    const long long stride = (long long)gridDim.x * blockDim.x;

    for (; k < N4; k += stride) {
        const int row     = (int)(k >> 11);          // 2048 float4 per row
        const int colbase = ((int)k & 2047) << 2;

        float4 v = make_float4(0.f, 0.f, 0.f, 0.f);

        // Diagonal element inside this float4?
        const unsigned d = (unsigned)(row - colbase);
        if (d < 4u) {
            v.x = (d == 0u) ? 1.f : 0.f;
            v.y = (d == 1u) ? 1.f : 0.f;
            v.z = (d == 2u) ? 1.f : 0.f;
            v.w = (d == 3u) ? 1.f : 0.f;
        }

        // 2x2 block entries: component 3 of colbase CB_I/CB_J in rows
        // CONN_I/CONN_J (<=4 threads take this branch).
        if ((row == CONN_I || row == CONN_J) &&
            (colbase == CB_I || colbase == CB_J)) {
            float eii, ejj, eij, eji;
            block_exp_real(bii[0], bjj[0], bij_real[0], bij_img[0],
                           eii, ejj, eij, eji);
            if (row == CONN_I)
                v.w = (colbase == CB_I) ? eii : eij;
            else
                v.w = (colbase == CB_I) ? eji : ejj;
        }

        __stcs(&out4[k], v);  // streaming store, evict-first
    }
}

// ---------------------------------------------------------------------------
// Fallback path (layout surprise): scalar-safe fill + patches.
// ---------------------------------------------------------------------------
__global__ void fill_zero_scalar(float* __restrict__ out, long long nfloats) {
    long long i = (long long)blockIdx.x * blockDim.x + threadIdx.x;
    const long long stride = (long long)gridDim.x * blockDim.x;
    for (; i < nfloats; i += stride) out[i] = 0.f;
}

__global__ void diag_kernel(float* __restrict__ out) {
    long long i = (long long)blockIdx.x * blockDim.x + threadIdx.x;
    if (i < N_CONST) out[i * (N_CONST + 1)] = 1.f;
}

__global__ void block_kernel(const float* __restrict__ bii,
                             const float* __restrict__ bjj,
                             const float* __restrict__ bij_real,
                             const float* __restrict__ bij_img,
                             float* __restrict__ out) {
    if (threadIdx.x != 0 || blockIdx.x != 0) return;
    float eii, ejj, eij, eji;
    block_exp_real(bii[0], bjj[0], bij_real[0], bij_img[0],
                   eii, ejj, eij, eji);
    out[(long long)CONN_I * N_CONST + CONN_I] = eii;
    out[(long long)CONN_J * N_CONST + CONN_J] = ejj;
    out[(long long)CONN_I * N_CONST + CONN_J] = eij;
    out[(long long)CONN_J * N_CONST + CONN_I] = eji;
}

extern "C" void kernel_launch(void* const* d_in, const int* in_sizes, int n_in,
                              void* d_out, int out_size) {
    if (n_in < 4) return;

    const float* bii      = (const float*)d_in[0];
    const float* bjj      = (const float*)d_in[1];
    const float* bij_real = (const float*)d_in[2];
    const float* bij_img  = (const float*)d_in[3];

    const bool aligned16 = (((uintptr_t)d_out) & 15u) == 0;
    const bool full      = ((long long)out_size == NN);

    if (aligned16 && full) {
        fused_fill_kernel<<<148 * 32, 256>>>(bii, bjj, bij_real, bij_img,
                                             (float4*)d_out);
    } else {
        float* outf = (float*)d_out;
        const long long nfloats = (long long)out_size;
        fill_zero_scalar<<<148 * 32, 256>>>(outf, nfloats);
        if (nfloats >= NN) {
            diag_kernel<<<(int)((N_CONST + 255) / 256), 256>>>(outf);
            block_kernel<<<1, 32>>>(bii, bjj, bij_real, bij_img, outf);
        }
    }
}

// round 11
// speedup vs baseline: 2.5034x; 1.3663x over previous
#include <cuda_runtime.h>
#include <cuda_bf16.h>
#include <math.h>
#include <stdint.h>

// ---------------------------------------------------------------------------
// Output = real part of V: 8192 x 8192 float32 (256 MiB). V = eye with
// closed-form 2x2 Hermitian block exp at (123, 4567).
//
// Proven configuration (R7, 41.1 us at normal clocks = DRAM-write drain
// floor; R10 measured the SAME code at 57 us under a throttled-clock hold):
//  * ONE fused kernel: zero-fill + diagonal + block patch, single STG.128
//    pass, grid 148*32 x 256, grid-stride, one float4 per thread per iter
//    (unit-stride within warp -> perfectly coalesced 4KB/warp-iteration).
//  * __stcs evict-first stores.
//  * NEW: #pragma unroll 4 on the grid-stride loop -> 4 independent STG.128
//    in flight per window, less loop ALU; helps when SM clock (not HBM) is
//    the binding resource. Coalescing unchanged (R9's failure was per-thread
//    consecutive pairs, NOT grid-stride unrolling).
// ---------------------------------------------------------------------------

static constexpr long long N_CONST = 8192;
static constexpr long long NN      = N_CONST * N_CONST;   // 67,108,864
static constexpr long long N4      = NN >> 2;             // 16,777,216 float4
static constexpr int       CONN_I  = 123;
static constexpr int       CONN_J  = 4567;
static constexpr int CB_I = (CONN_I / 4) * 4;   // 120
static constexpr int CB_J = (CONN_J / 4) * 4;   // 4564

// Closed-form real parts of exp(1j*H) for the 2x2 Hermitian block.
__device__ __forceinline__ void block_exp_real(
    float a, float b, float cr, float ci,
    float& eii_re, float& ejj_re, float& eij_re, float& eji_re) {
    const float t = 0.5f * (a + b);
    const float d = 0.5f * (a - b);
    const float r = sqrtf(d * d + cr * cr + ci * ci);
    const float sinc = (r > 0.f) ? (sinf(r) / r) : 1.f;
    const float cosr = cosf(r);
    float st, ct;
    sincosf(t, &st, &ct);
    eii_re = ct * cosr - st * (sinc * d);
    ejj_re = ct * cosr + st * (sinc * d);
    eij_re = ct * (-sinc * ci) - st * (sinc * cr);
    eji_re = ct * (sinc * ci) - st * (sinc * cr);
}

// Compute the value of the float4 at linear float4-index k.
__device__ __forceinline__ float4 value_at(
    long long k,
    const float* __restrict__ bii, const float* __restrict__ bjj,
    const float* __restrict__ bij_real, const float* __restrict__ bij_img) {
    const int row     = (int)(k >> 11);          // 2048 float4 per row
    const int colbase = ((int)k & 2047) << 2;

    float4 v = make_float4(0.f, 0.f, 0.f, 0.f);

    // Diagonal element inside this float4?
    const unsigned d = (unsigned)(row - colbase);
    if (d < 4u) {
        v.x = (d == 0u) ? 1.f : 0.f;
        v.y = (d == 1u) ? 1.f : 0.f;
        v.z = (d == 2u) ? 1.f : 0.f;
        v.w = (d == 3u) ? 1.f : 0.f;
    }

    // 2x2 block entries: component 3 of colbase CB_I/CB_J in rows
    // CONN_I/CONN_J (<=4 threads ever take this branch).
    if ((row == CONN_I || row == CONN_J) &&
        (colbase == CB_I || colbase == CB_J)) {
        float eii, ejj, eij, eji;
        block_exp_real(bii[0], bjj[0], bij_real[0], bij_img[0],
                       eii, ejj, eij, eji);
        if (row == CONN_I)
            v.w = (colbase == CB_I) ? eii : eij;
        else
            v.w = (colbase == CB_I) ? eji : ejj;
    }
    return v;
}

// ---------------------------------------------------------------------------
// Fused kernel: zero + diagonal + block patch, one pass of STG.128,
// grid-stride loop unrolled x4 (addresses within a warp stay unit-stride).
// ---------------------------------------------------------------------------
__global__ void fused_fill_kernel(const float* __restrict__ bii,
                                  const float* __restrict__ bjj,
                                  const float* __restrict__ bij_real,
                                  const float* __restrict__ bij_img,
                                  float4* __restrict__ out4) {
    long long k = (long long)blockIdx.x * blockDim.x + threadIdx.x;
    const long long stride = (long long)gridDim.x * blockDim.x;

#pragma unroll 4
    for (; k < N4; k += stride) {
        const float4 v = value_at(k, bii, bjj, bij_real, bij_img);
        __stcs(&out4[k], v);  // streaming store, evict-first
    }
}

// ---------------------------------------------------------------------------
// Fallback path (layout surprise): scalar-safe fill + patches.
// ---------------------------------------------------------------------------
__global__ void fill_zero_scalar(float* __restrict__ out, long long nfloats) {
    long long i = (long long)blockIdx.x * blockDim.x + threadIdx.x;
    const long long stride = (long long)gridDim.x * blockDim.x;
    for (; i < nfloats; i += stride) out[i] = 0.f;
}

__global__ void diag_kernel(float* __restrict__ out) {
    long long i = (long long)blockIdx.x * blockDim.x + threadIdx.x;
    if (i < N_CONST) out[i * (N_CONST + 1)] = 1.f;
}

__global__ void block_kernel(const float* __restrict__ bii,
                             const float* __restrict__ bjj,
                             const float* __restrict__ bij_real,
                             const float* __restrict__ bij_img,
                             float* __restrict__ out) {
    if (threadIdx.x != 0 || blockIdx.x != 0) return;
    float eii, ejj, eij, eji;
    block_exp_real(bii[0], bjj[0], bij_real[0], bij_img[0],
                   eii, ejj, eij, eji);
    out[(long long)CONN_I * N_CONST + CONN_I] = eii;
    out[(long long)CONN_J * N_CONST + CONN_J] = ejj;
    out[(long long)CONN_I * N_CONST + CONN_J] = eij;
    out[(long long)CONN_J * N_CONST + CONN_I] = eji;
}

extern "C" void kernel_launch(void* const* d_in, const int* in_sizes, int n_in,
                              void* d_out, int out_size) {
    if (n_in < 4) return;

    const float* bii      = (const float*)d_in[0];
    const float* bjj      = (const float*)d_in[1];
    const float* bij_real = (const float*)d_in[2];
    const float* bij_img  = (const float*)d_in[3];

    const bool aligned16 = (((uintptr_t)d_out) & 15u) == 0;
    const bool full      = ((long long)out_size == NN);

    if (aligned16 && full) {
        fused_fill_kernel<<<148 * 32, 256>>>(bii, bjj, bij_real, bij_img,
                                             (float4*)d_out);
    } else {
        float* outf = (float*)d_out;
        const long long nfloats = (long long)out_size;
        fill_zero_scalar<<<148 * 32, 256>>>(outf, nfloats);
        if (nfloats >= NN) {
            diag_kernel<<<(int)((N_CONST + 255) / 256), 256>>>(outf);
            block_kernel<<<1, 32>>>(bii, bjj, bij_real, bij_img, outf);
        }
    }
}

// round 12
// speedup vs baseline: 2.5208x; 1.0069x over previous
#include <cuda_runtime.h>
#include <cuda_bf16.h>
#include <math.h>
#include <stdint.h>

// ---------------------------------------------------------------------------
// V_l_51204600103593: output = real part of V, 8192 x 8192 float32 (256 MiB).
// V = eye(8192) with closed-form 2x2 Hermitian block exp at (123, 4567).
//
// CONVERGED configuration (best measured: 41.1 us, R7; re-verified R11):
//  * ONE fused kernel: zero-fill + diagonal + block patch in a single
//    STG.128 pass. Fusion saved ~6 us vs 3 kernels (R6->R7).
//  * grid 148*32 = 4736 blocks x 256 threads, grid-stride, ONE float4 per
//    thread per iteration -> unit-stride within each warp-iteration,
//    perfectly coalesced 4KB/warp. (R9: per-thread float4 pairs + small grid
//    de-coalesce the store stream -> 104 us. Never repeat.)
//  * __stcs evict-first stores (best measured; plain stores ~2% slower,
//    L2-retention split is a no-op on this harness: R6/R8).
//  * No unroll pragma (R11: neutral, +2 regs).
//
// Roofline: 268 MB written per replay at ~5.45 TB/s sustained write BW
// (~69% of 8 TB/s spec, the write-only ceiling) -> ~38.5 us kernel + ~3 us
// replay overhead. Issue/ALU/occupancy all have headroom; DRAM drain binds.
// ---------------------------------------------------------------------------

static constexpr long long N_CONST = 8192;
static constexpr long long NN      = N_CONST * N_CONST;   // 67,108,864
static constexpr long long N4      = NN >> 2;             // 16,777,216 float4
static constexpr int       CONN_I  = 123;
static constexpr int       CONN_J  = 4567;
static constexpr int CB_I = (CONN_I / 4) * 4;   // 120
static constexpr int CB_J = (CONN_J / 4) * 4;   // 4564

// Closed-form real parts of exp(1j*H) for the 2x2 Hermitian block.
__device__ __forceinline__ void block_exp_real(
    float a, float b, float cr, float ci,
    float& eii_re, float& ejj_re, float& eij_re, float& eji_re) {
    const float t = 0.5f * (a + b);
    const float d = 0.5f * (a - b);
    const float r = sqrtf(d * d + cr * cr + ci * ci);
    const float sinc = (r > 0.f) ? (sinf(r) / r) : 1.f;
    const float cosr = cosf(r);
    float st, ct;
    sincosf(t, &st, &ct);
    eii_re = ct * cosr - st * (sinc * d);
    ejj_re = ct * cosr + st * (sinc * d);
    eij_re = ct * (-sinc * ci) - st * (sinc * cr);
    eji_re = ct * (sinc * ci) - st * (sinc * cr);
}

// ---------------------------------------------------------------------------
// Fused kernel: zero + diagonal + block patch, one pass of STG.128.
// ---------------------------------------------------------------------------
__global__ void fused_fill_kernel(const float* __restrict__ bii,
                                  const float* __restrict__ bjj,
                                  const float* __restrict__ bij_real,
                                  const float* __restrict__ bij_img,
                                  float4* __restrict__ out4) {
    long long k = (long long)blockIdx.x * blockDim.x + threadIdx.x;
    const long long stride = (long long)gridDim.x * blockDim.x;

    for (; k < N4; k += stride) {
        const int row     = (int)(k >> 11);          // 2048 float4 per row
        const int colbase = ((int)k & 2047) << 2;

        float4 v = make_float4(0.f, 0.f, 0.f, 0.f);

        // Diagonal element inside this float4?
        const unsigned d = (unsigned)(row - colbase);
        if (d < 4u) {
            v.x = (d == 0u) ? 1.f : 0.f;
            v.y = (d == 1u) ? 1.f : 0.f;
            v.z = (d == 2u) ? 1.f : 0.f;
            v.w = (d == 3u) ? 1.f : 0.f;
        }

        // 2x2 block entries: component 3 of colbase CB_I/CB_J in rows
        // CONN_I/CONN_J (<=4 threads ever take this branch).
        if ((row == CONN_I || row == CONN_J) &&
            (colbase == CB_I || colbase == CB_J)) {
            float eii, ejj, eij, eji;
            block_exp_real(bii[0], bjj[0], bij_real[0], bij_img[0],
                           eii, ejj, eij, eji);
            if (row == CONN_I)
                v.w = (colbase == CB_I) ? eii : eij;
            else
                v.w = (colbase == CB_I) ? eji : ejj;
        }

        __stcs(&out4[k], v);  // streaming store, evict-first
    }
}

// ---------------------------------------------------------------------------
// Fallback path (layout surprise): scalar-safe fill + patches.
// ---------------------------------------------------------------------------
__global__ void fill_zero_scalar(float* __restrict__ out, long long nfloats) {
    long long i = (long long)blockIdx.x * blockDim.x + threadIdx.x;
    const long long stride = (long long)gridDim.x * blockDim.x;
    for (; i < nfloats; i += stride) out[i] = 0.f;
}

__global__ void diag_kernel(float* __restrict__ out) {
    long long i = (long long)blockIdx.x * blockDim.x + threadIdx.x;
    if (i < N_CONST) out[i * (N_CONST + 1)] = 1.f;
}

__global__ void block_kernel(const float* __restrict__ bii,
                             const float* __restrict__ bjj,
                             const float* __restrict__ bij_real,
                             const float* __restrict__ bij_img,
                             float* __restrict__ out) {
    if (threadIdx.x != 0 || blockIdx.x != 0) return;
    float eii, ejj, eij, eji;
    block_exp_real(bii[0], bjj[0], bij_real[0], bij_img[0],
                   eii, ejj, eij, eji);
    out[(long long)CONN_I * N_CONST + CONN_I] = eii;
    out[(long long)CONN_J * N_CONST + CONN_J] = ejj;
    out[(long long)CONN_I * N_CONST + CONN_J] = eij;
    out[(long long)CONN_J * N_CONST + CONN_I] = eji;
}

extern "C" void kernel_launch(void* const* d_in, const int* in_sizes, int n_in,
                              void* d_out, int out_size) {
    if (n_in < 4) return;

    const float* bii      = (const float*)d_in[0];
    const float* bjj      = (const float*)d_in[1];
    const float* bij_real = (const float*)d_in[2];
    const float* bij_img  = (const float*)d_in[3];

    const bool aligned16 = (((uintptr_t)d_out) & 15u) == 0;
    const bool full      = ((long long)out_size == NN);

    if (aligned16 && full) {
        fused_fill_kernel<<<148 * 32, 256>>>(bii, bjj, bij_real, bij_img,
                                             (float4*)d_out);
    } else {
        float* outf = (float*)d_out;
        const long long nfloats = (long long)out_size;
        fill_zero_scalar<<<148 * 32, 256>>>(outf, nfloats);
        if (nfloats >= NN) {
            diag_kernel<<<(int)((N_CONST + 255) / 256), 256>>>(outf);
            block_kernel<<<1, 32>>>(bii, bjj, bij_real, bij_img, outf);
        }
    }
}

// round 15
// speedup vs baseline: 2.5484x; 1.0109x over previous
#include <cuda_runtime.h>
#include <cuda_bf16.h>
#include <math.h>
#include <stdint.h>

// ---------------------------------------------------------------------------
// V_l_51204600103593: output = real part of V, 8192 x 8192 float32 (256 MiB).
// V = eye(8192) with closed-form 2x2 Hermitian block exp at (123, 4567).
//
// R12 observation: DRAM (67%) and L1 (69%) are near-equally loaded -> the
// L1/LSU store-wavefront path may co-bind with the DRAM drain. This round:
// Blackwell 256-bit stores (st.global.cs.v8.f32 -> STG.256), one 32B store
// per thread per iteration. Warp still covers a fully-dense contiguous 1KB
// (unlike R9's two separate STG.128 at strided lanes), but L1 wavefronts
// per byte are HALVED.
//
// Everything else is the proven R7/R11 configuration: single fused kernel,
// grid 148*32 x 256, grid-stride, evict-first stores.
// ---------------------------------------------------------------------------

static constexpr long long N_CONST = 8192;
static constexpr long long NN      = N_CONST * N_CONST;   // 67,108,864
static constexpr long long N8      = NN >> 3;             // 8,388,608 8-float chunks
static constexpr int       CONN_I  = 123;
static constexpr int       CONN_J  = 4567;
// 32B-chunk granularity: 1024 chunks per row of 8192 floats.
// col 123  -> chunkbase 120,  lane offset 3
// col 4567 -> chunkbase 4560, lane offset 7
static constexpr int KB_I  = (CONN_I / 8) * 8;   // 120
static constexpr int KB_J  = (CONN_J / 8) * 8;   // 4560
static constexpr int KO_I  = CONN_I % 8;         // 3
static constexpr int KO_J  = CONN_J % 8;         // 7

// Closed-form real parts of exp(1j*H) for the 2x2 Hermitian block.
__device__ __forceinline__ void block_exp_real(
    float a, float b, float cr, float ci,
    float& eii_re, float& ejj_re, float& eij_re, float& eji_re) {
    const float t = 0.5f * (a + b);
    const float d = 0.5f * (a - b);
    const float r = sqrtf(d * d + cr * cr + ci * ci);
    const float sinc = (r > 0.f) ? (sinf(r) / r) : 1.f;
    const float cosr = cosf(r);
    float st, ct;
    sincosf(t, &st, &ct);
    eii_re = ct * cosr - st * (sinc * d);
    ejj_re = ct * cosr + st * (sinc * d);
    eij_re = ct * (-sinc * ci) - st * (sinc * cr);
    eji_re = ct * (sinc * ci) - st * (sinc * cr);
}

// 256-bit streaming store (Blackwell STG.256, evict-first).
__device__ __forceinline__ void stg256_cs(float* __restrict__ p,
                                          float v0, float v1, float v2, float v3,
                                          float v4, float v5, float v6, float v7) {
    asm volatile(
        "st.global.cs.v8.f32 [%0], {%1, %2, %3, %4, %5, %6, %7, %8};"
        :: "l"(p),
           "f"(v0), "f"(v1), "f"(v2), "f"(v3),
           "f"(v4), "f"(v5), "f"(v6), "f"(v7)
        : "memory");
}

// ---------------------------------------------------------------------------
// Fused kernel: zero + diagonal + block patch, one pass of STG.256.
// ---------------------------------------------------------------------------
__global__ void fused_fill_kernel(const float* __restrict__ bii,
                                  const float* __restrict__ bjj,
                                  const float* __restrict__ bij_real,
                                  const float* __restrict__ bij_img,
                                  float* __restrict__ out) {
    long long k = (long long)blockIdx.x * blockDim.x + threadIdx.x;
    const long long stride = (long long)gridDim.x * blockDim.x;

    for (; k < N8; k += stride) {
        const int row       = (int)(k >> 10);          // 1024 chunks per row
        const int chunkbase = ((int)k & 1023) << 3;    // first of 8 columns

        float v0 = 0.f, v1 = 0.f, v2 = 0.f, v3 = 0.f;
        float v4 = 0.f, v5 = 0.f, v6 = 0.f, v7 = 0.f;

        // Diagonal element among these 8 columns?
        const unsigned d = (unsigned)(row - chunkbase);
        if (d < 8u) {
            v0 = (d == 0u) ? 1.f : 0.f;
            v1 = (d == 1u) ? 1.f : 0.f;
            v2 = (d == 2u) ? 1.f : 0.f;
            v3 = (d == 3u) ? 1.f : 0.f;
            v4 = (d == 4u) ? 1.f : 0.f;
            v5 = (d == 5u) ? 1.f : 0.f;
            v6 = (d == 6u) ? 1.f : 0.f;
            v7 = (d == 7u) ? 1.f : 0.f;
        }

        // 2x2 block entries (taken by <=2 threads total):
        //   (123,123)  = eii @ row 123,  chunk 120  offset 3
        //   (123,4567) = eij @ row 123,  chunk 4560 offset 7
        //   (4567,123) = eji @ row 4567, chunk 120  offset 3
        //   (4567,4567)= ejj @ row 4567, chunk 4560 offset 7
        if ((row == CONN_I || row == CONN_J) &&
            (chunkbase == KB_I || chunkbase == KB_J)) {
            float eii, ejj, eij, eji;
            block_exp_real(bii[0], bjj[0], bij_real[0], bij_img[0],
                           eii, ejj, eij, eji);
            if (row == CONN_I) {
                if (chunkbase == KB_I) v3 = eii;   // KO_I = 3
                else                   v7 = eij;   // KO_J = 7
            } else {
                if (chunkbase == KB_I) v3 = eji;
                else                   v7 = ejj;
            }
        }

        stg256_cs(out + (k << 3), v0, v1, v2, v3, v4, v5, v6, v7);
    }
}

// ---------------------------------------------------------------------------
// Fallback path (layout surprise): scalar-safe fill + patches.
// ---------------------------------------------------------------------------
__global__ void fill_zero_scalar(float* __restrict__ out, long long nfloats) {
    long long i = (long long)blockIdx.x * blockDim.x + threadIdx.x;
    const long long stride = (long long)gridDim.x * blockDim.x;
    for (; i < nfloats; i += stride) out[i] = 0.f;
}

__global__ void diag_kernel(float* __restrict__ out) {
    long long i = (long long)blockIdx.x * blockDim.x + threadIdx.x;
    if (i < N_CONST) out[i * (N_CONST + 1)] = 1.f;
}

__global__ void block_kernel(const float* __restrict__ bii,
                             const float* __restrict__ bjj,
                             const float* __restrict__ bij_real,
                             const float* __restrict__ bij_img,
                             float* __restrict__ out) {
    if (threadIdx.x != 0 || blockIdx.x != 0) return;
    float eii, ejj, eij, eji;
    block_exp_real(bii[0], bjj[0], bij_real[0], bij_img[0],
                   eii, ejj, eij, eji);
    out[(long long)CONN_I * N_CONST + CONN_I] = eii;
    out[(long long)CONN_J * N_CONST + CONN_J] = ejj;
    out[(long long)CONN_I * N_CONST + CONN_J] = eij;
    out[(long long)CONN_J * N_CONST + CONN_I] = eji;
}

extern "C" void kernel_launch(void* const* d_in, const int* in_sizes, int n_in,
                              void* d_out, int out_size) {
    if (n_in < 4) return;

    const float* bii      = (const float*)d_in[0];
    const float* bjj      = (const float*)d_in[1];
    const float* bij_real = (const float*)d_in[2];
    const float* bij_img  = (const float*)d_in[3];

    const bool aligned32 = (((uintptr_t)d_out) & 31u) == 0;
    const bool full      = ((long long)out_size == NN);

    if (aligned32 && full) {
        fused_fill_kernel<<<148 * 32, 256>>>(bii, bjj, bij_real, bij_img,
                                             (float*)d_out);
    } else {
        float* outf = (float*)d_out;
        const long long nfloats = (long long)out_size;
        fill_zero_scalar<<<148 * 32, 256>>>(outf, nfloats);
        if (nfloats >= NN) {
            diag_kernel<<<(int)((N_CONST + 255) / 256), 256>>>(outf);
            block_kernel<<<1, 32>>>(bii, bjj, bij_real, bij_img, outf);
        }
    }
}